// round 15
// baseline (speedup 1.0000x reference)
#include <cuda_runtime.h>
#include <math.h>

typedef unsigned long long u64;

#define BB   512
#define LL   512
#define VV   50000
#define EE   100
#define HH   100
#define GG   400
#define HIDN 50
#define KK   20
#define STARTK 18
#define ENDK   19
#define NEGV  (-1e6f)

// ---------------- scratch (device globals) ----------------------------------
__device__ float g_embproj[2][VV][GG];     // gate-interleaved [v][4q+m], bias folded
__device__ float g_h[2][BB][LL][HH];       // hf / hb (hb already un-reversed)
__device__ int   g_task_ctr;

extern __shared__ float smem_dyn[];

__device__ __forceinline__ float sigf(float x) {
    return __fdividef(1.0f, 1.0f + __expf(-x));
}
__device__ __forceinline__ float tanf_fast(float x) {
    return 1.0f - __fdividef(2.0f, __expf(2.0f * x) + 1.0f);
}

__device__ __forceinline__ u64 fma2(u64 a, u64 b, u64 c) {
    u64 d; asm("fma.rn.f32x2 %0, %1, %2, %3;" : "=l"(d) : "l"(a), "l"(b), "l"(c)); return d;
}
__device__ __forceinline__ u64 pk2(float lo, float hi) {
    u64 r; asm("mov.b64 %0, {%1, %2};" : "=l"(r) : "f"(lo), "f"(hi)); return r;
}
__device__ __forceinline__ void up2(u64 v, float& lo, float& hi) {
    asm("mov.b64 {%0, %1}, %2;" : "=f"(lo), "=f"(hi) : "l"(v));
}

// ---------------- K1: embproj[v][4q+m] = dot(emb[v], Wih[q+100m]) + b -------
// Also resets the LSTM task counter (replaces the zero_ctr launch).
__global__ void embproj_kernel(const float* __restrict__ emb,
                               const float* __restrict__ Wih_f, const float* __restrict__ b_f,
                               const float* __restrict__ Wih_b, const float* __restrict__ b_b)
{
    if (blockIdx.x == 0 && blockIdx.y == 0 && threadIdx.x == 0) g_task_ctr = 0;

    const int dir = blockIdx.y;
    const float* Wih  = dir ? Wih_b : Wih_f;
    const float* bias = dir ? b_b   : b_f;

    float*  WihT  = smem_dyn;             // [100][400] gate-interleaved: [e][4q+m]
    float*  bperm = WihT + 40000;         // [400]
    float4* ed4   = (float4*)(bperm + 400); // dup-pairs

    const int tid = threadIdx.x;
    for (int i = tid; i < 40000; i += 256) {
        int e = i / 400, g = i - e * 400;
        int q = g >> 2, m = g & 3;
        WihT[i] = Wih[(q + 100 * m) * EE + e];
    }
    for (int i = tid; i < 400; i += 256) {
        int q = i >> 2, m = i & 3;
        bperm[i] = bias[q + 100 * m];
    }

    const int vbase = blockIdx.x * 128;
    const int grp = tid / 100;
    const int q   = tid - grp * 100;
    const bool active = (tid < 200);

    for (int g0 = 0; g0 < 16; g0++) {
        const int vb = vbase + g0 * 8;
        __syncthreads();
        for (int i = tid; i < 400; i += 256) {
            int gi = i / 200, rem = i - gi * 200;
            int e = rem >> 1, p = rem & 1;
            int v0 = vb + gi * 4 + p * 2;
            float a0 = (v0 < VV)     ? emb[(size_t)v0 * EE + e]       : 0.0f;
            float a1 = (v0 + 1 < VV) ? emb[(size_t)(v0 + 1) * EE + e] : 0.0f;
            ed4[(gi * 100 + e) * 2 + p] = make_float4(a0, a0, a1, a1);
        }
        __syncthreads();
        if (active) {
            u64 bif = pk2(bperm[4*q], bperm[4*q+1]);
            u64 bgo = pk2(bperm[4*q+2], bperm[4*q+3]);
            u64 aif[4] = {bif, bif, bif, bif};
            u64 ago[4] = {bgo, bgo, bgo, bgo};
            const ulonglong2* wb = (const ulonglong2*)(WihT + 4 * q);
            const ulonglong2* xb = (const ulonglong2*)ed4 + grp * 200;
            #pragma unroll 4
            for (int e = 0; e < 100; e++) {
                ulonglong2 w2  = wb[e * 100];
                ulonglong2 x01 = xb[e * 2];
                ulonglong2 x23 = xb[e * 2 + 1];
                aif[0] = fma2(w2.x, x01.x, aif[0]); ago[0] = fma2(w2.y, x01.x, ago[0]);
                aif[1] = fma2(w2.x, x01.y, aif[1]); ago[1] = fma2(w2.y, x01.y, ago[1]);
                aif[2] = fma2(w2.x, x23.x, aif[2]); ago[2] = fma2(w2.y, x23.x, ago[2]);
                aif[3] = fma2(w2.x, x23.y, aif[3]); ago[3] = fma2(w2.y, x23.y, ago[3]);
            }
            #pragma unroll
            for (int r = 0; r < 4; r++) {
                int v = vb + grp * 4 + r;
                if (v < VV)
                    *reinterpret_cast<ulonglong2*>(&g_embproj[dir][v][4 * q]) =
                        make_ulonglong2(aif[r], ago[r]);
            }
        }
    }
}

// ---------------- K2: work-stealing persistent BiLSTM, 4-row tasks ----------
// (round-7 best config: 256 threads, LPT task order, single counter)
__global__ void __launch_bounds__(256, 1)
lstm_kernel(const int* __restrict__ X, const int* __restrict__ lengths,
            const float* __restrict__ Whh_f, const float* __restrict__ Whh_b,
            const float* __restrict__ h0, const float* __restrict__ c0)
{
    float* Wf   = smem_dyn;                    // 40000 floats
    float* hf   = smem_dyn + 40000;            // 800 floats: 2 buffers x 400
    int*   toks = (int*)(smem_dyn + 40800);    // [4][512]
    int*   task_s = toks + 4 * 512;            // [1]

    const int tx = threadIdx.x;
    const bool active = (tx < 200);
    const int q     = tx >> 1;
    const int rbase = (tx & 1) * 2;            // activation rows: even->0-1, odd->2-3
    unsigned wmask = 0;
    {
        int nact = 200 - (tx >> 5) * 32;
        if (nact > 0) wmask = (nact >= 32) ? 0xffffffffu : ((1u << nact) - 1u);
    }

    int prev_dir = -1;
    for (;;) {
        if (tx == 0) task_s[0] = atomicAdd(&g_task_ctr, 1);
        __syncthreads();
        const int task = task_s[0];
        __syncthreads();                       // protect task_s before next overwrite
        if (task >= 256) break;

        const int dir = task & 1;              // LPT order: interleave dirs
        const int rowbase = (task >> 1) * 4;
        const int grouplen = lengths[rowbase]; // max of group (sorted desc)

        if (dir != prev_dir) {
            const float* Whh = dir ? Whh_b : Whh_f;
            for (int i = tx; i < 40000; i += 256) {
                int u = i >> 1, j = i & 1;
                int kp = u / 400, s = u - kp * 400;
                int qq = s >> 2, m = s & 3;
                Wf[i] = Whh[(qq + 100 * m) * HH + 2 * kp + j];
            }
            prev_dir = dir;
        }
        for (int i = tx; i < 4 * 512; i += 256) {
            int r = i >> 9, t = i & 511;
            int b = rowbase + r;
            int len = lengths[b];
            int idx = dir ? ((t < len) ? (len - 1 - t) : t) : t;
            toks[i] = X[b * LL + idx];
        }

        float c[2]; int len2[2]; float* outp[2];
        if (active) {
            #pragma unroll
            for (int rr = 0; rr < 2; rr++) {
                int r = rbase + rr, b = rowbase + r;
                len2[rr] = lengths[b];
                c[rr] = c0[(dir * BB + b) * HH + q];
                hf[(q >> 1) * 8 + r * 2 + (q & 1)] = h0[(dir * BB + b) * HH + q];
                outp[rr] = &g_h[dir][b][0][q];
            }
        }
        __syncthreads();

        const u64* EP = (const u64*)&g_embproj[dir][0][0];   // [v][200] u64
        u64 nx[4];
        if (active) {
            #pragma unroll
            for (int r = 0; r < 4; r++)
                nx[r] = EP[(size_t)toks[r * 512] * 200 + tx];
        }

        int cur = 0;
        for (int t = 0; t < grouplen; t++) {
            if (active) {
                u64 a0[4], a1[4];
                #pragma unroll
                for (int r = 0; r < 4; r++) {
                    float e0, e1; up2(nx[r], e0, e1);
                    a0[r] = pk2(e0, 0.0f);
                    a1[r] = pk2(e1, 0.0f);
                }
                if (t + 1 < grouplen) {
                    #pragma unroll
                    for (int r = 0; r < 4; r++)
                        nx[r] = EP[(size_t)toks[r * 512 + t + 1] * 200 + tx];
                }

                const ulonglong2* Wv = (const ulonglong2*)Wf;             // kp*200+tx
                const ulonglong2* hv = (const ulonglong2*)hf + cur * 100; // 100 u2/buf
                #pragma unroll 5
                for (int kp = 0; kp < 50; kp++) {
                    ulonglong2 w2  = Wv[kp * 200 + tx];
                    ulonglong2 h01 = hv[kp * 2 + 0];   // (h0,h0'),(h1,h1') pairs
                    ulonglong2 h23 = hv[kp * 2 + 1];
                    a0[0] = fma2(w2.x, h01.x, a0[0]); a1[0] = fma2(w2.y, h01.x, a1[0]);
                    a0[1] = fma2(w2.x, h01.y, a0[1]); a1[1] = fma2(w2.y, h01.y, a1[1]);
                    a0[2] = fma2(w2.x, h23.x, a0[2]); a1[2] = fma2(w2.y, h23.x, a1[2]);
                    a0[3] = fma2(w2.x, h23.y, a0[3]); a1[3] = fma2(w2.y, h23.y, a1[3]);
                }

                float A[4], B[4], shA[4], shB[4];
                #pragma unroll
                for (int r = 0; r < 4; r++) {
                    float lo, hi;
                    up2(a0[r], lo, hi); A[r] = lo + hi;
                    up2(a1[r], lo, hi); B[r] = lo + hi;
                }
                #pragma unroll
                for (int r = 0; r < 4; r++) {
                    shA[r] = __shfl_xor_sync(wmask, A[r], 1);
                    shB[r] = __shfl_xor_sync(wmask, B[r], 1);
                }

                const bool odd = (tx & 1);
                const int nb = cur ^ 1;
                #pragma unroll
                for (int rr = 0; rr < 2; rr++) {
                    int r = rbase + rr;
                    float iv = odd ? shA[r] : A[r];
                    float fv = odd ? shB[r] : B[r];
                    float gv = odd ? A[r]  : shA[r];
                    float ov = odd ? B[r]  : shB[r];
                    float cn = sigf(fv) * c[rr] + sigf(iv) * tanf_fast(gv);
                    c[rr] = cn;
                    float hn = sigf(ov) * tanf_fast(cn);
                    hf[nb * 400 + (q >> 1) * 8 + r * 2 + (q & 1)] = hn;
                    int pos = dir ? ((t < len2[rr]) ? (len2[rr] - 1 - t) : t) : t;
                    outp[rr][pos * HH] = hn;
                }
            }
            __syncthreads();
            cur ^= 1;
        }
    }
}

// ---------------- K3: fused MLP + Viterbi, one block per batch row ----------
// 256 threads compute the row's 512x20 probs into smem (math byte-identical
// to the previous mlp_kernel), then warp 0 runs the identical Viterbi.
__global__ void __launch_bounds__(256, 2)
mlp_vit_kernel(const int* __restrict__ lengths,
               const float* __restrict__ W1, const float* __restrict__ b1,
               const float* __restrict__ W2, const float* __restrict__ b2,
               const float* __restrict__ trans, float* __restrict__ out)
{
    float* W1Ts   = smem_dyn;          // [200][52], pad j 50->52 with zeros
    float* W2Ts   = W1Ts + 10400;      // [50][20]
    float* b1s    = W2Ts + 1000;       // [52]
    float* b2s    = b1s + 52;          // [20]
    float* ps     = b2s + 20;          // [512*20]
    float* path_s = ps + 10240;        // [512]
    signed char* bp = (signed char*)(path_s + 512);  // [512*20]

    const int tid = threadIdx.x;
    const int b   = blockIdx.x;
    const int len = lengths[b];

    for (int i = tid; i < 10400; i += 256) {
        int k = i / 52, j = i - k * 52;
        W1Ts[i] = (j < 50) ? W1[j * 200 + k] : 0.0f;
    }
    for (int i = tid; i < 1000; i += 256) {
        int j = i / 20, k2 = i - j * 20;
        W2Ts[i] = W2[k2 * 50 + j];
    }
    if (tid < 52) b1s[tid] = (tid < 50) ? b1[tid] : 0.0f;
    if (tid < 20) b2s[tid] = b2[tid];
    __syncthreads();

    // ---- phase 1: probs for 2 tokens per thread (sequential, regs bounded) --
    for (int it = 0; it < 2; it++) {
        const int t = it * 256 + tid;
        if (t >= len) continue;

        u64 acc[26];
        #pragma unroll
        for (int p = 0; p < 26; p++) acc[p] = pk2(b1s[2 * p], b1s[2 * p + 1]);

        #pragma unroll
        for (int half = 0; half < 2; half++) {
            const float4* g = (const float4*)&g_h[half][b][t][0];
            #pragma unroll 2
            for (int cchunk = 0; cchunk < 25; cchunk++) {
                float4 ex = g[cchunk];
                #pragma unroll
                for (int u = 0; u < 4; u++) {
                    float x = (u == 0) ? ex.x : (u == 1) ? ex.y : (u == 2) ? ex.z : ex.w;
                    int k = half * 100 + cchunk * 4 + u;
                    u64 xd = pk2(x, x);
                    const ulonglong2* wr = (const ulonglong2*)&W1Ts[k * 52];
                    #pragma unroll
                    for (int p = 0; p < 13; p++) {
                        ulonglong2 wv = wr[p];
                        acc[2 * p]     = fma2(wv.x, xd, acc[2 * p]);
                        acc[2 * p + 1] = fma2(wv.y, xd, acc[2 * p + 1]);
                    }
                }
            }
        }

        u64 a2[10];
        #pragma unroll
        for (int p = 0; p < 10; p++) a2[p] = pk2(b2s[2 * p], b2s[2 * p + 1]);

        #pragma unroll
        for (int p = 0; p < 25; p++) {
            float ha, hb2;
            up2(acc[p], ha, hb2);
            ha  = fmaxf(ha, 0.0f);
            hb2 = fmaxf(hb2, 0.0f);
            u64 hd0 = pk2(ha, ha), hd1 = pk2(hb2, hb2);
            const ulonglong2* w0 = (const ulonglong2*)&W2Ts[(2 * p) * 20];
            const ulonglong2* w1 = (const ulonglong2*)&W2Ts[(2 * p + 1) * 20];
            #pragma unroll
            for (int pp = 0; pp < 5; pp++) {
                ulonglong2 wv0 = w0[pp];
                a2[2 * pp]     = fma2(wv0.x, hd0, a2[2 * pp]);
                a2[2 * pp + 1] = fma2(wv0.y, hd0, a2[2 * pp + 1]);
            }
            #pragma unroll
            for (int pp = 0; pp < 5; pp++) {
                ulonglong2 wv1 = w1[pp];
                a2[2 * pp]     = fma2(wv1.x, hd1, a2[2 * pp]);
                a2[2 * pp + 1] = fma2(wv1.y, hd1, a2[2 * pp + 1]);
            }
        }

        float o[20];
        #pragma unroll
        for (int p = 0; p < 10; p++) up2(a2[p], o[2 * p], o[2 * p + 1]);
        float4* op = (float4*)&ps[t * 20];
        #pragma unroll
        for (int p = 0; p < 5; p++)
            op[p] = make_float4(o[4 * p], o[4 * p + 1], o[4 * p + 2], o[4 * p + 3]);
    }
    __syncthreads();

    // ---- phase 2: Viterbi on warp 0 (identical logic) -----------------------
    if (tid >= 32) return;

    const int k2 = (tid < 20) ? tid : 19;
    float tr[20];
    #pragma unroll
    for (int k1 = 0; k1 < 20; k1++) tr[k1] = trans[k1 * 20 + k2];
    const float trE = trans[k2 * 20 + ENDK];

    float alpha = (tid == STARTK) ? 0.0f : NEGV;
    __syncwarp();
    float pcur = ps[k2];

    for (int t = 0; t < len; t++) {
        float pnext = (t + 1 < len) ? ps[(t + 1) * 20 + k2] : 0.0f;
        float vv[20];
        #pragma unroll
        for (int k1 = 0; k1 < 20; k1++)
            vv[k1] = (__shfl_sync(0xffffffffu, alpha, k1) + tr[k1]) + pcur;

        float v0 = vv[0]; int i0 = 0;
        #pragma unroll
        for (int i = 1; i < 5; i++)  if (vv[i] > v0) { v0 = vv[i]; i0 = i; }
        float v1 = vv[5]; int i1 = 5;
        #pragma unroll
        for (int i = 6; i < 10; i++) if (vv[i] > v1) { v1 = vv[i]; i1 = i; }
        float v2 = vv[10]; int i2 = 10;
        #pragma unroll
        for (int i = 11; i < 15; i++) if (vv[i] > v2) { v2 = vv[i]; i2 = i; }
        float v3 = vv[15]; int i3 = 15;
        #pragma unroll
        for (int i = 16; i < 20; i++) if (vv[i] > v3) { v3 = vv[i]; i3 = i; }
        if (v1 > v0) { v0 = v1; i0 = i1; }
        if (v3 > v2) { v2 = v3; i2 = i3; }
        if (v2 > v0) { v0 = v2; i0 = i2; }

        if (tid < 20) bp[t * 20 + tid] = (signed char)i0;
        alpha = v0;
        pcur = pnext;
    }

    float fin = alpha + trE;
    float fv[20];
    #pragma unroll
    for (int k = 0; k < 20; k++) fv[k] = __shfl_sync(0xffffffffu, fin, k);
    float v0 = fv[0]; int i0 = 0;
    #pragma unroll
    for (int i = 1; i < 20; i++) if (fv[i] > v0) { v0 = fv[i]; i0 = i; }

    if (tid == 0) {
        out[b] = v0;
        int c = i0;
        for (int t = 511; t >= 0; t--) {
            if (t < len) { path_s[t] = (float)c; c = bp[t * 20 + c]; }
            else path_s[t] = -1.0f;
        }
    }
    __syncwarp();
    for (int t = tid; t < 512; t += 32) out[BB + (size_t)b * 512 + t] = path_s[t];
}

// ---------------- launch ----------------------------------------------------
extern "C" void kernel_launch(void* const* d_in, const int* in_sizes, int n_in,
                              void* d_out, int out_size)
{
    const int*   X       = (const int*)  d_in[0];
    const int*   lengths = (const int*)  d_in[1];
    const float* emb     = (const float*)d_in[2];
    const float* Wih_f   = (const float*)d_in[3];
    const float* Whh_f   = (const float*)d_in[4];
    const float* b_f     = (const float*)d_in[5];
    const float* Wih_b   = (const float*)d_in[6];
    const float* Whh_b   = (const float*)d_in[7];
    const float* b_b     = (const float*)d_in[8];
    const float* h0      = (const float*)d_in[9];
    const float* c0      = (const float*)d_in[10];
    const float* W1      = (const float*)d_in[11];
    const float* b1      = (const float*)d_in[12];
    const float* W2      = (const float*)d_in[13];
    const float* b2      = (const float*)d_in[14];
    const float* trans   = (const float*)d_in[15];
    float* out = (float*)d_out;

    const int EMB_SMEM  = (40000 + 400 + 1600) * 4;              // 168000
    const int LSTM_SMEM = (40000 + 800) * 4 + (4 * 512 + 1) * 4; // 171396
    const int MV_SMEM   = (10400 + 1000 + 52 + 20 + 10240 + 512) * 4 + 10240; // 99136

    cudaFuncSetAttribute(embproj_kernel, cudaFuncAttributeMaxDynamicSharedMemorySize, EMB_SMEM);
    cudaFuncSetAttribute(lstm_kernel,    cudaFuncAttributeMaxDynamicSharedMemorySize, LSTM_SMEM);
    cudaFuncSetAttribute(mlp_vit_kernel, cudaFuncAttributeMaxDynamicSharedMemorySize, MV_SMEM);

    embproj_kernel<<<dim3(391, 2, 1), 256, EMB_SMEM>>>(emb, Wih_f, b_f, Wih_b, b_b);
    lstm_kernel<<<148, 256, LSTM_SMEM>>>(X, lengths, Whh_f, Whh_b, h0, c0);
    mlp_vit_kernel<<<512, 256, MV_SMEM>>>(lengths, W1, b1, W2, b2, trans, out);
}

// round 16
// speedup vs baseline: 1.0014x; 1.0014x over previous
#include <cuda_runtime.h>
#include <math.h>

typedef unsigned long long u64;

#define BB   512
#define LL   512
#define VV   50000
#define EE   100
#define HH   100
#define GG   400
#define HIDN 50
#define KK   20
#define STARTK 18
#define ENDK   19
#define NEGV  (-1e6f)

// ---------------- scratch (device globals) ----------------------------------
__device__ float g_embproj[2][VV][GG];     // gate-interleaved [v][4q+m], bias folded
__device__ float g_h[2][BB][LL][HH];       // hf / hb (hb already un-reversed)
__device__ int   g_task_ctr;

extern __shared__ float smem_dyn[];

__device__ __forceinline__ float sigf(float x) {
    return __fdividef(1.0f, 1.0f + __expf(-x));
}
__device__ __forceinline__ float tanf_fast(float x) {
    return 1.0f - __fdividef(2.0f, __expf(2.0f * x) + 1.0f);
}

__device__ __forceinline__ u64 fma2(u64 a, u64 b, u64 c) {
    u64 d; asm("fma.rn.f32x2 %0, %1, %2, %3;" : "=l"(d) : "l"(a), "l"(b), "l"(c)); return d;
}
__device__ __forceinline__ u64 pk2(float lo, float hi) {
    u64 r; asm("mov.b64 %0, {%1, %2};" : "=l"(r) : "f"(lo), "f"(hi)); return r;
}
__device__ __forceinline__ void up2(u64 v, float& lo, float& hi) {
    asm("mov.b64 {%0, %1}, %2;" : "=f"(lo), "=f"(hi) : "l"(v));
}

// ---------------- K1: embproj[v][4q+m] = dot(emb[v], Wih[q+100m]) + b -------
// Also resets the LSTM task counter (replaces the zero_ctr launch).
__global__ void embproj_kernel(const float* __restrict__ emb,
                               const float* __restrict__ Wih_f, const float* __restrict__ b_f,
                               const float* __restrict__ Wih_b, const float* __restrict__ b_b)
{
    if (blockIdx.x == 0 && blockIdx.y == 0 && threadIdx.x == 0) g_task_ctr = 0;

    const int dir = blockIdx.y;
    const float* Wih  = dir ? Wih_b : Wih_f;
    const float* bias = dir ? b_b   : b_f;

    float*  WihT  = smem_dyn;             // [100][400] gate-interleaved: [e][4q+m]
    float*  bperm = WihT + 40000;         // [400]
    float4* ed4   = (float4*)(bperm + 400); // dup-pairs

    const int tid = threadIdx.x;
    for (int i = tid; i < 40000; i += 256) {
        int e = i / 400, g = i - e * 400;
        int q = g >> 2, m = g & 3;
        WihT[i] = Wih[(q + 100 * m) * EE + e];
    }
    for (int i = tid; i < 400; i += 256) {
        int q = i >> 2, m = i & 3;
        bperm[i] = bias[q + 100 * m];
    }

    const int vbase = blockIdx.x * 128;
    const int grp = tid / 100;
    const int q   = tid - grp * 100;
    const bool active = (tid < 200);

    for (int g0 = 0; g0 < 16; g0++) {
        const int vb = vbase + g0 * 8;
        __syncthreads();
        for (int i = tid; i < 400; i += 256) {
            int gi = i / 200, rem = i - gi * 200;
            int e = rem >> 1, p = rem & 1;
            int v0 = vb + gi * 4 + p * 2;
            float a0 = (v0 < VV)     ? emb[(size_t)v0 * EE + e]       : 0.0f;
            float a1 = (v0 + 1 < VV) ? emb[(size_t)(v0 + 1) * EE + e] : 0.0f;
            ed4[(gi * 100 + e) * 2 + p] = make_float4(a0, a0, a1, a1);
        }
        __syncthreads();
        if (active) {
            u64 bif = pk2(bperm[4*q], bperm[4*q+1]);
            u64 bgo = pk2(bperm[4*q+2], bperm[4*q+3]);
            u64 aif[4] = {bif, bif, bif, bif};
            u64 ago[4] = {bgo, bgo, bgo, bgo};
            const ulonglong2* wb = (const ulonglong2*)(WihT + 4 * q);
            const ulonglong2* xb = (const ulonglong2*)ed4 + grp * 200;
            #pragma unroll 4
            for (int e = 0; e < 100; e++) {
                ulonglong2 w2  = wb[e * 100];
                ulonglong2 x01 = xb[e * 2];
                ulonglong2 x23 = xb[e * 2 + 1];
                aif[0] = fma2(w2.x, x01.x, aif[0]); ago[0] = fma2(w2.y, x01.x, ago[0]);
                aif[1] = fma2(w2.x, x01.y, aif[1]); ago[1] = fma2(w2.y, x01.y, ago[1]);
                aif[2] = fma2(w2.x, x23.x, aif[2]); ago[2] = fma2(w2.y, x23.x, ago[2]);
                aif[3] = fma2(w2.x, x23.y, aif[3]); ago[3] = fma2(w2.y, x23.y, ago[3]);
            }
            #pragma unroll
            for (int r = 0; r < 4; r++) {
                int v = vb + grp * 4 + r;
                if (v < VV)
                    *reinterpret_cast<ulonglong2*>(&g_embproj[dir][v][4 * q]) =
                        make_ulonglong2(aif[r], ago[r]);
            }
        }
    }
}

// ---------------- K2: work-stealing persistent BiLSTM, 4-row tasks ----------
// (round-7 best config: 256 threads, LPT task order, single counter)
__global__ void __launch_bounds__(256, 1)
lstm_kernel(const int* __restrict__ X, const int* __restrict__ lengths,
            const float* __restrict__ Whh_f, const float* __restrict__ Whh_b,
            const float* __restrict__ h0, const float* __restrict__ c0)
{
    float* Wf   = smem_dyn;                    // 40000 floats
    float* hf   = smem_dyn + 40000;            // 800 floats: 2 buffers x 400
    int*   toks = (int*)(smem_dyn + 40800);    // [4][512]
    int*   task_s = toks + 4 * 512;            // [1]

    const int tx = threadIdx.x;
    const bool active = (tx < 200);
    const int q     = tx >> 1;
    const int rbase = (tx & 1) * 2;            // activation rows: even->0-1, odd->2-3
    unsigned wmask = 0;
    {
        int nact = 200 - (tx >> 5) * 32;
        if (nact > 0) wmask = (nact >= 32) ? 0xffffffffu : ((1u << nact) - 1u);
    }

    int prev_dir = -1;
    for (;;) {
        if (tx == 0) task_s[0] = atomicAdd(&g_task_ctr, 1);
        __syncthreads();
        const int task = task_s[0];
        __syncthreads();                       // protect task_s before next overwrite
        if (task >= 256) break;

        const int dir = task & 1;              // LPT order: interleave dirs
        const int rowbase = (task >> 1) * 4;
        const int grouplen = lengths[rowbase]; // max of group (sorted desc)

        if (dir != prev_dir) {
            const float* Whh = dir ? Whh_b : Whh_f;
            for (int i = tx; i < 40000; i += 256) {
                int u = i >> 1, j = i & 1;
                int kp = u / 400, s = u - kp * 400;
                int qq = s >> 2, m = s & 3;
                Wf[i] = Whh[(qq + 100 * m) * HH + 2 * kp + j];
            }
            prev_dir = dir;
        }
        for (int i = tx; i < 4 * 512; i += 256) {
            int r = i >> 9, t = i & 511;
            int b = rowbase + r;
            int len = lengths[b];
            int idx = dir ? ((t < len) ? (len - 1 - t) : t) : t;
            toks[i] = X[b * LL + idx];
        }

        float c[2]; int len2[2]; float* outp[2];
        if (active) {
            #pragma unroll
            for (int rr = 0; rr < 2; rr++) {
                int r = rbase + rr, b = rowbase + r;
                len2[rr] = lengths[b];
                c[rr] = c0[(dir * BB + b) * HH + q];
                hf[(q >> 1) * 8 + r * 2 + (q & 1)] = h0[(dir * BB + b) * HH + q];
                outp[rr] = &g_h[dir][b][0][q];
            }
        }
        __syncthreads();

        const u64* EP = (const u64*)&g_embproj[dir][0][0];   // [v][200] u64
        u64 nx[4];
        if (active) {
            #pragma unroll
            for (int r = 0; r < 4; r++)
                nx[r] = EP[(size_t)toks[r * 512] * 200 + tx];
        }

        int cur = 0;
        for (int t = 0; t < grouplen; t++) {
            if (active) {
                u64 a0[4], a1[4];
                #pragma unroll
                for (int r = 0; r < 4; r++) {
                    float e0, e1; up2(nx[r], e0, e1);
                    a0[r] = pk2(e0, 0.0f);
                    a1[r] = pk2(e1, 0.0f);
                }
                if (t + 1 < grouplen) {
                    #pragma unroll
                    for (int r = 0; r < 4; r++)
                        nx[r] = EP[(size_t)toks[r * 512 + t + 1] * 200 + tx];
                }

                const ulonglong2* Wv = (const ulonglong2*)Wf;             // kp*200+tx
                const ulonglong2* hv = (const ulonglong2*)hf + cur * 100; // 100 u2/buf
                #pragma unroll 5
                for (int kp = 0; kp < 50; kp++) {
                    ulonglong2 w2  = Wv[kp * 200 + tx];
                    ulonglong2 h01 = hv[kp * 2 + 0];   // (h0,h0'),(h1,h1') pairs
                    ulonglong2 h23 = hv[kp * 2 + 1];
                    a0[0] = fma2(w2.x, h01.x, a0[0]); a1[0] = fma2(w2.y, h01.x, a1[0]);
                    a0[1] = fma2(w2.x, h01.y, a0[1]); a1[1] = fma2(w2.y, h01.y, a1[1]);
                    a0[2] = fma2(w2.x, h23.x, a0[2]); a1[2] = fma2(w2.y, h23.x, a1[2]);
                    a0[3] = fma2(w2.x, h23.y, a0[3]); a1[3] = fma2(w2.y, h23.y, a1[3]);
                }

                float A[4], B[4], shA[4], shB[4];
                #pragma unroll
                for (int r = 0; r < 4; r++) {
                    float lo, hi;
                    up2(a0[r], lo, hi); A[r] = lo + hi;
                    up2(a1[r], lo, hi); B[r] = lo + hi;
                }
                #pragma unroll
                for (int r = 0; r < 4; r++) {
                    shA[r] = __shfl_xor_sync(wmask, A[r], 1);
                    shB[r] = __shfl_xor_sync(wmask, B[r], 1);
                }

                const bool odd = (tx & 1);
                const int nb = cur ^ 1;
                #pragma unroll
                for (int rr = 0; rr < 2; rr++) {
                    int r = rbase + rr;
                    float iv = odd ? shA[r] : A[r];
                    float fv = odd ? shB[r] : B[r];
                    float gv = odd ? A[r]  : shA[r];
                    float ov = odd ? B[r]  : shB[r];
                    float cn = sigf(fv) * c[rr] + sigf(iv) * tanf_fast(gv);
                    c[rr] = cn;
                    float hn = sigf(ov) * tanf_fast(cn);
                    hf[nb * 400 + (q >> 1) * 8 + r * 2 + (q & 1)] = hn;
                    int pos = dir ? ((t < len2[rr]) ? (len2[rr] - 1 - t) : t) : t;
                    outp[rr][pos * HH] = hn;
                }
            }
            __syncthreads();
            cur ^= 1;
        }
    }
}

// ---------------- K3: fused MLP + Viterbi, one block per batch row ----------
// 256 threads compute the row's 512x20 probs into smem (math byte-identical
// to the previous mlp_kernel), then warp 0 runs the identical Viterbi.
__global__ void __launch_bounds__(256, 2)
mlp_vit_kernel(const int* __restrict__ lengths,
               const float* __restrict__ W1, const float* __restrict__ b1,
               const float* __restrict__ W2, const float* __restrict__ b2,
               const float* __restrict__ trans, float* __restrict__ out)
{
    float* W1Ts   = smem_dyn;          // [200][52], pad j 50->52 with zeros
    float* W2Ts   = W1Ts + 10400;      // [50][20]
    float* b1s    = W2Ts + 1000;       // [52]
    float* b2s    = b1s + 52;          // [20]
    float* ps     = b2s + 20;          // [512*20]
    float* path_s = ps + 10240;        // [512]
    signed char* bp = (signed char*)(path_s + 512);  // [512*20]

    const int tid = threadIdx.x;
    const int b   = blockIdx.x;
    const int len = lengths[b];

    for (int i = tid; i < 10400; i += 256) {
        int k = i / 52, j = i - k * 52;
        W1Ts[i] = (j < 50) ? W1[j * 200 + k] : 0.0f;
    }
    for (int i = tid; i < 1000; i += 256) {
        int j = i / 20, k2 = i - j * 20;
        W2Ts[i] = W2[k2 * 50 + j];
    }
    if (tid < 52) b1s[tid] = (tid < 50) ? b1[tid] : 0.0f;
    if (tid < 20) b2s[tid] = b2[tid];
    __syncthreads();

    // ---- phase 1: probs for 2 tokens per thread (sequential, regs bounded) --
    for (int it = 0; it < 2; it++) {
        const int t = it * 256 + tid;
        if (t >= len) continue;

        u64 acc[26];
        #pragma unroll
        for (int p = 0; p < 26; p++) acc[p] = pk2(b1s[2 * p], b1s[2 * p + 1]);

        #pragma unroll
        for (int half = 0; half < 2; half++) {
            const float4* g = (const float4*)&g_h[half][b][t][0];
            #pragma unroll 2
            for (int cchunk = 0; cchunk < 25; cchunk++) {
                float4 ex = g[cchunk];
                #pragma unroll
                for (int u = 0; u < 4; u++) {
                    float x = (u == 0) ? ex.x : (u == 1) ? ex.y : (u == 2) ? ex.z : ex.w;
                    int k = half * 100 + cchunk * 4 + u;
                    u64 xd = pk2(x, x);
                    const ulonglong2* wr = (const ulonglong2*)&W1Ts[k * 52];
                    #pragma unroll
                    for (int p = 0; p < 13; p++) {
                        ulonglong2 wv = wr[p];
                        acc[2 * p]     = fma2(wv.x, xd, acc[2 * p]);
                        acc[2 * p + 1] = fma2(wv.y, xd, acc[2 * p + 1]);
                    }
                }
            }
        }

        u64 a2[10];
        #pragma unroll
        for (int p = 0; p < 10; p++) a2[p] = pk2(b2s[2 * p], b2s[2 * p + 1]);

        #pragma unroll
        for (int p = 0; p < 25; p++) {
            float ha, hb2;
            up2(acc[p], ha, hb2);
            ha  = fmaxf(ha, 0.0f);
            hb2 = fmaxf(hb2, 0.0f);
            u64 hd0 = pk2(ha, ha), hd1 = pk2(hb2, hb2);
            const ulonglong2* w0 = (const ulonglong2*)&W2Ts[(2 * p) * 20];
            const ulonglong2* w1 = (const ulonglong2*)&W2Ts[(2 * p + 1) * 20];
            #pragma unroll
            for (int pp = 0; pp < 5; pp++) {
                ulonglong2 wv0 = w0[pp];
                a2[2 * pp]     = fma2(wv0.x, hd0, a2[2 * pp]);
                a2[2 * pp + 1] = fma2(wv0.y, hd0, a2[2 * pp + 1]);
            }
            #pragma unroll
            for (int pp = 0; pp < 5; pp++) {
                ulonglong2 wv1 = w1[pp];
                a2[2 * pp]     = fma2(wv1.x, hd1, a2[2 * pp]);
                a2[2 * pp + 1] = fma2(wv1.y, hd1, a2[2 * pp + 1]);
            }
        }

        float o[20];
        #pragma unroll
        for (int p = 0; p < 10; p++) up2(a2[p], o[2 * p], o[2 * p + 1]);
        float4* op = (float4*)&ps[t * 20];
        #pragma unroll
        for (int p = 0; p < 5; p++)
            op[p] = make_float4(o[4 * p], o[4 * p + 1], o[4 * p + 2], o[4 * p + 3]);
    }
    __syncthreads();

    // ---- phase 2: Viterbi on warp 0 (identical logic) -----------------------
    if (tid >= 32) return;

    const int k2 = (tid < 20) ? tid : 19;
    float tr[20];
    #pragma unroll
    for (int k1 = 0; k1 < 20; k1++) tr[k1] = trans[k1 * 20 + k2];
    const float trE = trans[k2 * 20 + ENDK];

    float alpha = (tid == STARTK) ? 0.0f : NEGV;
    __syncwarp();
    float pcur = ps[k2];

    for (int t = 0; t < len; t++) {
        float pnext = (t + 1 < len) ? ps[(t + 1) * 20 + k2] : 0.0f;
        float vv[20];
        #pragma unroll
        for (int k1 = 0; k1 < 20; k1++)
            vv[k1] = (__shfl_sync(0xffffffffu, alpha, k1) + tr[k1]) + pcur;

        float v0 = vv[0]; int i0 = 0;
        #pragma unroll
        for (int i = 1; i < 5; i++)  if (vv[i] > v0) { v0 = vv[i]; i0 = i; }
        float v1 = vv[5]; int i1 = 5;
        #pragma unroll
        for (int i = 6; i < 10; i++) if (vv[i] > v1) { v1 = vv[i]; i1 = i; }
        float v2 = vv[10]; int i2 = 10;
        #pragma unroll
        for (int i = 11; i < 15; i++) if (vv[i] > v2) { v2 = vv[i]; i2 = i; }
        float v3 = vv[15]; int i3 = 15;
        #pragma unroll
        for (int i = 16; i < 20; i++) if (vv[i] > v3) { v3 = vv[i]; i3 = i; }
        if (v1 > v0) { v0 = v1; i0 = i1; }
        if (v3 > v2) { v2 = v3; i2 = i3; }
        if (v2 > v0) { v0 = v2; i0 = i2; }

        if (tid < 20) bp[t * 20 + tid] = (signed char)i0;
        alpha = v0;
        pcur = pnext;
    }

    float fin = alpha + trE;
    float fv[20];
    #pragma unroll
    for (int k = 0; k < 20; k++) fv[k] = __shfl_sync(0xffffffffu, fin, k);
    float v0 = fv[0]; int i0 = 0;
    #pragma unroll
    for (int i = 1; i < 20; i++) if (fv[i] > v0) { v0 = fv[i]; i0 = i; }

    if (tid == 0) {
        out[b] = v0;
        int c = i0;
        for (int t = 511; t >= 0; t--) {
            if (t < len) { path_s[t] = (float)c; c = bp[t * 20 + c]; }
            else path_s[t] = -1.0f;
        }
    }
    __syncwarp();
    for (int t = tid; t < 512; t += 32) out[BB + (size_t)b * 512 + t] = path_s[t];
}

// ---------------- launch ----------------------------------------------------
extern "C" void kernel_launch(void* const* d_in, const int* in_sizes, int n_in,
                              void* d_out, int out_size)
{
    const int*   X       = (const int*)  d_in[0];
    const int*   lengths = (const int*)  d_in[1];
    const float* emb     = (const float*)d_in[2];
    const float* Wih_f   = (const float*)d_in[3];
    const float* Whh_f   = (const float*)d_in[4];
    const float* b_f     = (const float*)d_in[5];
    const float* Wih_b   = (const float*)d_in[6];
    const float* Whh_b   = (const float*)d_in[7];
    const float* b_b     = (const float*)d_in[8];
    const float* h0      = (const float*)d_in[9];
    const float* c0      = (const float*)d_in[10];
    const float* W1      = (const float*)d_in[11];
    const float* b1      = (const float*)d_in[12];
    const float* W2      = (const float*)d_in[13];
    const float* b2      = (const float*)d_in[14];
    const float* trans   = (const float*)d_in[15];
    float* out = (float*)d_out;

    const int EMB_SMEM  = (40000 + 400 + 1600) * 4;              // 168000
    const int LSTM_SMEM = (40000 + 800) * 4 + (4 * 512 + 1) * 4; // 171396
    const int MV_SMEM   = (10400 + 1000 + 52 + 20 + 10240 + 512) * 4 + 10240; // 99136

    cudaFuncSetAttribute(embproj_kernel, cudaFuncAttributeMaxDynamicSharedMemorySize, EMB_SMEM);
    cudaFuncSetAttribute(lstm_kernel,    cudaFuncAttributeMaxDynamicSharedMemorySize, LSTM_SMEM);
    cudaFuncSetAttribute(mlp_vit_kernel, cudaFuncAttributeMaxDynamicSharedMemorySize, MV_SMEM);

    embproj_kernel<<<dim3(391, 2, 1), 256, EMB_SMEM>>>(emb, Wih_f, b_f, Wih_b, b_b);
    lstm_kernel<<<148, 256, LSTM_SMEM>>>(X, lengths, Whh_f, Whh_b, h0, c0);
    mlp_vit_kernel<<<512, 256, MV_SMEM>>>(lengths, W1, b1, W2, b2, trans, out);
}

// round 17
// speedup vs baseline: 1.0150x; 1.0136x over previous
#include <cuda_runtime.h>
#include <math.h>

typedef unsigned long long u64;

#define BB   512
#define LL   512
#define VV   50000
#define EE   100
#define HH   100
#define GG   400
#define HIDN 50
#define KK   20
#define STARTK 18
#define ENDK   19
#define NEGV  (-1e6f)

// ---------------- scratch (device globals) ----------------------------------
__device__ float g_embproj[2][VV][GG];     // gate-interleaved [v][4q+m], bias folded
__device__ float g_h[2][BB][LL][HH];       // hf / hb (hb already un-reversed)
__device__ int   g_task_ctr;

extern __shared__ float smem_dyn[];

__device__ __forceinline__ float sigf(float x) {
    return __fdividef(1.0f, 1.0f + __expf(-x));
}
__device__ __forceinline__ float tanf_fast(float x) {
    return 1.0f - __fdividef(2.0f, __expf(2.0f * x) + 1.0f);
}

__device__ __forceinline__ u64 fma2(u64 a, u64 b, u64 c) {
    u64 d; asm("fma.rn.f32x2 %0, %1, %2, %3;" : "=l"(d) : "l"(a), "l"(b), "l"(c)); return d;
}
__device__ __forceinline__ u64 pk2(float lo, float hi) {
    u64 r; asm("mov.b64 %0, {%1, %2};" : "=l"(r) : "f"(lo), "f"(hi)); return r;
}
__device__ __forceinline__ void up2(u64 v, float& lo, float& hi) {
    asm("mov.b64 {%0, %1}, %2;" : "=f"(lo), "=f"(hi) : "l"(v));
}

// ---------------- K1: embproj, one-wave + double-buffered staging -----------
// grid (74, 2): block owns 680 vocab rows = 85 groups of 8. Threads 200-255
// prefetch the next group's dup-pair staging while 0-199 compute. Per-v math
// (group-of-8 structure, e-loop order) is byte-identical to previous rounds.
#define VPB  680
#define NGRP 85
__global__ void embproj_kernel(const float* __restrict__ emb,
                               const float* __restrict__ Wih_f, const float* __restrict__ b_f,
                               const float* __restrict__ Wih_b, const float* __restrict__ b_b)
{
    if (blockIdx.x == 0 && blockIdx.y == 0 && threadIdx.x == 0) g_task_ctr = 0;

    const int dir = blockIdx.y;
    const float* Wih  = dir ? Wih_b : Wih_f;
    const float* bias = dir ? b_b   : b_f;

    float*  WihT  = smem_dyn;             // [100][400] gate-interleaved: [e][4q+m]
    float*  bperm = WihT + 40000;         // [400]
    float4* ed4   = (float4*)(bperm + 400); // 2 buffers x 400 float4 dup-pairs

    const int tid = threadIdx.x;
    for (int i = tid; i < 40000; i += 256) {
        int e = i / 400, g = i - e * 400;
        int q = g >> 2, m = g & 3;
        WihT[i] = Wih[(q + 100 * m) * EE + e];
    }
    for (int i = tid; i < 400; i += 256) {
        int q = i >> 2, m = i & 3;
        bperm[i] = bias[q + 100 * m];
    }

    const int vbase = blockIdx.x * VPB;
    const int grp = tid / 100;
    const int q   = tid - grp * 100;
    const bool active = (tid < 200);

    // stage group 0 into buffer 0 (all threads)
    for (int i = tid; i < 400; i += 256) {
        int gi = i / 200, rem = i - gi * 200;
        int e = rem >> 1, p = rem & 1;
        int v0 = vbase + gi * 4 + p * 2;
        float a0 = (v0 < VV)     ? emb[(size_t)v0 * EE + e]       : 0.0f;
        float a1 = (v0 + 1 < VV) ? emb[(size_t)(v0 + 1) * EE + e] : 0.0f;
        ed4[(gi * 100 + e) * 2 + p] = make_float4(a0, a0, a1, a1);
    }
    __syncthreads();

    for (int g0 = 0; g0 < NGRP; g0++) {
        const int vb = vbase + g0 * 8;
        if (active) {
            u64 bif = pk2(bperm[4*q], bperm[4*q+1]);
            u64 bgo = pk2(bperm[4*q+2], bperm[4*q+3]);
            u64 aif[4] = {bif, bif, bif, bif};
            u64 ago[4] = {bgo, bgo, bgo, bgo};
            const ulonglong2* wb = (const ulonglong2*)(WihT + 4 * q);
            const ulonglong2* xb = (const ulonglong2*)ed4 + (g0 & 1) * 400 + grp * 200;
            #pragma unroll 4
            for (int e = 0; e < 100; e++) {
                ulonglong2 w2  = wb[e * 100];
                ulonglong2 x01 = xb[e * 2];
                ulonglong2 x23 = xb[e * 2 + 1];
                aif[0] = fma2(w2.x, x01.x, aif[0]); ago[0] = fma2(w2.y, x01.x, ago[0]);
                aif[1] = fma2(w2.x, x01.y, aif[1]); ago[1] = fma2(w2.y, x01.y, ago[1]);
                aif[2] = fma2(w2.x, x23.x, aif[2]); ago[2] = fma2(w2.y, x23.x, ago[2]);
                aif[3] = fma2(w2.x, x23.y, aif[3]); ago[3] = fma2(w2.y, x23.y, ago[3]);
            }
            #pragma unroll
            for (int r = 0; r < 4; r++) {
                int v = vb + grp * 4 + r;
                if (v < VV)
                    *reinterpret_cast<ulonglong2*>(&g_embproj[dir][v][4 * q]) =
                        make_ulonglong2(aif[r], ago[r]);
            }
        } else if (g0 + 1 < NGRP) {
            // staging crew: prefetch group g0+1 into the alternate buffer
            const int vbn = vb + 8;
            float4* dst = ed4 + ((g0 + 1) & 1) * 400;
            for (int i = tid - 200; i < 400; i += 56) {
                int gi = i / 200, rem = i - gi * 200;
                int e = rem >> 1, p = rem & 1;
                int v0 = vbn + gi * 4 + p * 2;
                float a0 = (v0 < VV)     ? emb[(size_t)v0 * EE + e]       : 0.0f;
                float a1 = (v0 + 1 < VV) ? emb[(size_t)(v0 + 1) * EE + e] : 0.0f;
                dst[(gi * 100 + e) * 2 + p] = make_float4(a0, a0, a1, a1);
            }
        }
        __syncthreads();
    }
}

// ---------------- K2: work-stealing persistent BiLSTM, 4-row tasks ----------
// (round-7 best config: 256 threads, LPT task order, single counter)
__global__ void __launch_bounds__(256, 1)
lstm_kernel(const int* __restrict__ X, const int* __restrict__ lengths,
            const float* __restrict__ Whh_f, const float* __restrict__ Whh_b,
            const float* __restrict__ h0, const float* __restrict__ c0)
{
    float* Wf   = smem_dyn;                    // 40000 floats
    float* hf   = smem_dyn + 40000;            // 800 floats: 2 buffers x 400
    int*   toks = (int*)(smem_dyn + 40800);    // [4][512]
    int*   task_s = toks + 4 * 512;            // [1]

    const int tx = threadIdx.x;
    const bool active = (tx < 200);
    const int q     = tx >> 1;
    const int rbase = (tx & 1) * 2;            // activation rows: even->0-1, odd->2-3
    unsigned wmask = 0;
    {
        int nact = 200 - (tx >> 5) * 32;
        if (nact > 0) wmask = (nact >= 32) ? 0xffffffffu : ((1u << nact) - 1u);
    }

    int prev_dir = -1;
    for (;;) {
        if (tx == 0) task_s[0] = atomicAdd(&g_task_ctr, 1);
        __syncthreads();
        const int task = task_s[0];
        __syncthreads();                       // protect task_s before next overwrite
        if (task >= 256) break;

        const int dir = task & 1;              // LPT order: interleave dirs
        const int rowbase = (task >> 1) * 4;
        const int grouplen = lengths[rowbase]; // max of group (sorted desc)

        if (dir != prev_dir) {
            const float* Whh = dir ? Whh_b : Whh_f;
            for (int i = tx; i < 40000; i += 256) {
                int u = i >> 1, j = i & 1;
                int kp = u / 400, s = u - kp * 400;
                int qq = s >> 2, m = s & 3;
                Wf[i] = Whh[(qq + 100 * m) * HH + 2 * kp + j];
            }
            prev_dir = dir;
        }
        for (int i = tx; i < 4 * 512; i += 256) {
            int r = i >> 9, t = i & 511;
            int b = rowbase + r;
            int len = lengths[b];
            int idx = dir ? ((t < len) ? (len - 1 - t) : t) : t;
            toks[i] = X[b * LL + idx];
        }

        float c[2]; int len2[2]; float* outp[2];
        if (active) {
            #pragma unroll
            for (int rr = 0; rr < 2; rr++) {
                int r = rbase + rr, b = rowbase + r;
                len2[rr] = lengths[b];
                c[rr] = c0[(dir * BB + b) * HH + q];
                hf[(q >> 1) * 8 + r * 2 + (q & 1)] = h0[(dir * BB + b) * HH + q];
                outp[rr] = &g_h[dir][b][0][q];
            }
        }
        __syncthreads();

        const u64* EP = (const u64*)&g_embproj[dir][0][0];   // [v][200] u64
        u64 nx[4];
        if (active) {
            #pragma unroll
            for (int r = 0; r < 4; r++)
                nx[r] = EP[(size_t)toks[r * 512] * 200 + tx];
        }

        int cur = 0;
        for (int t = 0; t < grouplen; t++) {
            if (active) {
                u64 a0[4], a1[4];
                #pragma unroll
                for (int r = 0; r < 4; r++) {
                    float e0, e1; up2(nx[r], e0, e1);
                    a0[r] = pk2(e0, 0.0f);
                    a1[r] = pk2(e1, 0.0f);
                }
                if (t + 1 < grouplen) {
                    #pragma unroll
                    for (int r = 0; r < 4; r++)
                        nx[r] = EP[(size_t)toks[r * 512 + t + 1] * 200 + tx];
                }

                const ulonglong2* Wv = (const ulonglong2*)Wf;             // kp*200+tx
                const ulonglong2* hv = (const ulonglong2*)hf + cur * 100; // 100 u2/buf
                #pragma unroll 5
                for (int kp = 0; kp < 50; kp++) {
                    ulonglong2 w2  = Wv[kp * 200 + tx];
                    ulonglong2 h01 = hv[kp * 2 + 0];   // (h0,h0'),(h1,h1') pairs
                    ulonglong2 h23 = hv[kp * 2 + 1];
                    a0[0] = fma2(w2.x, h01.x, a0[0]); a1[0] = fma2(w2.y, h01.x, a1[0]);
                    a0[1] = fma2(w2.x, h01.y, a0[1]); a1[1] = fma2(w2.y, h01.y, a1[1]);
                    a0[2] = fma2(w2.x, h23.x, a0[2]); a1[2] = fma2(w2.y, h23.x, a1[2]);
                    a0[3] = fma2(w2.x, h23.y, a0[3]); a1[3] = fma2(w2.y, h23.y, a1[3]);
                }

                float A[4], B[4], shA[4], shB[4];
                #pragma unroll
                for (int r = 0; r < 4; r++) {
                    float lo, hi;
                    up2(a0[r], lo, hi); A[r] = lo + hi;
                    up2(a1[r], lo, hi); B[r] = lo + hi;
                }
                #pragma unroll
                for (int r = 0; r < 4; r++) {
                    shA[r] = __shfl_xor_sync(wmask, A[r], 1);
                    shB[r] = __shfl_xor_sync(wmask, B[r], 1);
                }

                const bool odd = (tx & 1);
                const int nb = cur ^ 1;
                #pragma unroll
                for (int rr = 0; rr < 2; rr++) {
                    int r = rbase + rr;
                    float iv = odd ? shA[r] : A[r];
                    float fv = odd ? shB[r] : B[r];
                    float gv = odd ? A[r]  : shA[r];
                    float ov = odd ? B[r]  : shB[r];
                    float cn = sigf(fv) * c[rr] + sigf(iv) * tanf_fast(gv);
                    c[rr] = cn;
                    float hn = sigf(ov) * tanf_fast(cn);
                    hf[nb * 400 + (q >> 1) * 8 + r * 2 + (q & 1)] = hn;
                    int pos = dir ? ((t < len2[rr]) ? (len2[rr] - 1 - t) : t) : t;
                    outp[rr][pos * HH] = hn;
                }
            }
            __syncthreads();
            cur ^= 1;
        }
    }
}

// ---------------- K3: fused MLP + Viterbi, one block per batch row ----------
__global__ void __launch_bounds__(256, 2)
mlp_vit_kernel(const int* __restrict__ lengths,
               const float* __restrict__ W1, const float* __restrict__ b1,
               const float* __restrict__ W2, const float* __restrict__ b2,
               const float* __restrict__ trans, float* __restrict__ out)
{
    float* W1Ts   = smem_dyn;          // [200][52], pad j 50->52 with zeros
    float* W2Ts   = W1Ts + 10400;      // [50][20]
    float* b1s    = W2Ts + 1000;       // [52]
    float* b2s    = b1s + 52;          // [20]
    float* ps     = b2s + 20;          // [512*20]
    float* path_s = ps + 10240;        // [512]
    signed char* bp = (signed char*)(path_s + 512);  // [512*20]

    const int tid = threadIdx.x;
    const int b   = blockIdx.x;
    const int len = lengths[b];

    for (int i = tid; i < 10400; i += 256) {
        int k = i / 52, j = i - k * 52;
        W1Ts[i] = (j < 50) ? W1[j * 200 + k] : 0.0f;
    }
    for (int i = tid; i < 1000; i += 256) {
        int j = i / 20, k2 = i - j * 20;
        W2Ts[i] = W2[k2 * 50 + j];
    }
    if (tid < 52) b1s[tid] = (tid < 50) ? b1[tid] : 0.0f;
    if (tid < 20) b2s[tid] = b2[tid];
    __syncthreads();

    for (int it = 0; it < 2; it++) {
        const int t = it * 256 + tid;
        if (t >= len) continue;

        u64 acc[26];
        #pragma unroll
        for (int p = 0; p < 26; p++) acc[p] = pk2(b1s[2 * p], b1s[2 * p + 1]);

        #pragma unroll
        for (int half = 0; half < 2; half++) {
            const float4* g = (const float4*)&g_h[half][b][t][0];
            #pragma unroll 2
            for (int cchunk = 0; cchunk < 25; cchunk++) {
                float4 ex = g[cchunk];
                #pragma unroll
                for (int u = 0; u < 4; u++) {
                    float x = (u == 0) ? ex.x : (u == 1) ? ex.y : (u == 2) ? ex.z : ex.w;
                    int k = half * 100 + cchunk * 4 + u;
                    u64 xd = pk2(x, x);
                    const ulonglong2* wr = (const ulonglong2*)&W1Ts[k * 52];
                    #pragma unroll
                    for (int p = 0; p < 13; p++) {
                        ulonglong2 wv = wr[p];
                        acc[2 * p]     = fma2(wv.x, xd, acc[2 * p]);
                        acc[2 * p + 1] = fma2(wv.y, xd, acc[2 * p + 1]);
                    }
                }
            }
        }

        u64 a2[10];
        #pragma unroll
        for (int p = 0; p < 10; p++) a2[p] = pk2(b2s[2 * p], b2s[2 * p + 1]);

        #pragma unroll
        for (int p = 0; p < 25; p++) {
            float ha, hb2;
            up2(acc[p], ha, hb2);
            ha  = fmaxf(ha, 0.0f);
            hb2 = fmaxf(hb2, 0.0f);
            u64 hd0 = pk2(ha, ha), hd1 = pk2(hb2, hb2);
            const ulonglong2* w0 = (const ulonglong2*)&W2Ts[(2 * p) * 20];
            const ulonglong2* w1 = (const ulonglong2*)&W2Ts[(2 * p + 1) * 20];
            #pragma unroll
            for (int pp = 0; pp < 5; pp++) {
                ulonglong2 wv0 = w0[pp];
                a2[2 * pp]     = fma2(wv0.x, hd0, a2[2 * pp]);
                a2[2 * pp + 1] = fma2(wv0.y, hd0, a2[2 * pp + 1]);
            }
            #pragma unroll
            for (int pp = 0; pp < 5; pp++) {
                ulonglong2 wv1 = w1[pp];
                a2[2 * pp]     = fma2(wv1.x, hd1, a2[2 * pp]);
                a2[2 * pp + 1] = fma2(wv1.y, hd1, a2[2 * pp + 1]);
            }
        }

        float o[20];
        #pragma unroll
        for (int p = 0; p < 10; p++) up2(a2[p], o[2 * p], o[2 * p + 1]);
        float4* op = (float4*)&ps[t * 20];
        #pragma unroll
        for (int p = 0; p < 5; p++)
            op[p] = make_float4(o[4 * p], o[4 * p + 1], o[4 * p + 2], o[4 * p + 3]);
    }
    __syncthreads();

    if (tid >= 32) return;

    const int k2 = (tid < 20) ? tid : 19;
    float tr[20];
    #pragma unroll
    for (int k1 = 0; k1 < 20; k1++) tr[k1] = trans[k1 * 20 + k2];
    const float trE = trans[k2 * 20 + ENDK];

    float alpha = (tid == STARTK) ? 0.0f : NEGV;
    __syncwarp();
    float pcur = ps[k2];

    for (int t = 0; t < len; t++) {
        float pnext = (t + 1 < len) ? ps[(t + 1) * 20 + k2] : 0.0f;
        float vv[20];
        #pragma unroll
        for (int k1 = 0; k1 < 20; k1++)
            vv[k1] = (__shfl_sync(0xffffffffu, alpha, k1) + tr[k1]) + pcur;

        float v0 = vv[0]; int i0 = 0;
        #pragma unroll
        for (int i = 1; i < 5; i++)  if (vv[i] > v0) { v0 = vv[i]; i0 = i; }
        float v1 = vv[5]; int i1 = 5;
        #pragma unroll
        for (int i = 6; i < 10; i++) if (vv[i] > v1) { v1 = vv[i]; i1 = i; }
        float v2 = vv[10]; int i2 = 10;
        #pragma unroll
        for (int i = 11; i < 15; i++) if (vv[i] > v2) { v2 = vv[i]; i2 = i; }
        float v3 = vv[15]; int i3 = 15;
        #pragma unroll
        for (int i = 16; i < 20; i++) if (vv[i] > v3) { v3 = vv[i]; i3 = i; }
        if (v1 > v0) { v0 = v1; i0 = i1; }
        if (v3 > v2) { v2 = v3; i2 = i3; }
        if (v2 > v0) { v0 = v2; i0 = i2; }

        if (tid < 20) bp[t * 20 + tid] = (signed char)i0;
        alpha = v0;
        pcur = pnext;
    }

    float fin = alpha + trE;
    float fv[20];
    #pragma unroll
    for (int k = 0; k < 20; k++) fv[k] = __shfl_sync(0xffffffffu, fin, k);
    float v0 = fv[0]; int i0 = 0;
    #pragma unroll
    for (int i = 1; i < 20; i++) if (fv[i] > v0) { v0 = fv[i]; i0 = i; }

    if (tid == 0) {
        out[b] = v0;
        int c = i0;
        for (int t = 511; t >= 0; t--) {
            if (t < len) { path_s[t] = (float)c; c = bp[t * 20 + c]; }
            else path_s[t] = -1.0f;
        }
    }
    __syncwarp();
    for (int t = tid; t < 512; t += 32) out[BB + (size_t)b * 512 + t] = path_s[t];
}

// ---------------- launch ----------------------------------------------------
extern "C" void kernel_launch(void* const* d_in, const int* in_sizes, int n_in,
                              void* d_out, int out_size)
{
    const int*   X       = (const int*)  d_in[0];
    const int*   lengths = (const int*)  d_in[1];
    const float* emb     = (const float*)d_in[2];
    const float* Wih_f   = (const float*)d_in[3];
    const float* Whh_f   = (const float*)d_in[4];
    const float* b_f     = (const float*)d_in[5];
    const float* Wih_b   = (const float*)d_in[6];
    const float* Whh_b   = (const float*)d_in[7];
    const float* b_b     = (const float*)d_in[8];
    const float* h0      = (const float*)d_in[9];
    const float* c0      = (const float*)d_in[10];
    const float* W1      = (const float*)d_in[11];
    const float* b1      = (const float*)d_in[12];
    const float* W2      = (const float*)d_in[13];
    const float* b2      = (const float*)d_in[14];
    const float* trans   = (const float*)d_in[15];
    float* out = (float*)d_out;

    const int EMB_SMEM  = (40000 + 400 + 3200) * 4;              // 174400
    const int LSTM_SMEM = (40000 + 800) * 4 + (4 * 512 + 1) * 4; // 171396
    const int MV_SMEM   = (10400 + 1000 + 52 + 20 + 10240 + 512) * 4 + 10240; // 99136

    cudaFuncSetAttribute(embproj_kernel, cudaFuncAttributeMaxDynamicSharedMemorySize, EMB_SMEM);
    cudaFuncSetAttribute(lstm_kernel,    cudaFuncAttributeMaxDynamicSharedMemorySize, LSTM_SMEM);
    cudaFuncSetAttribute(mlp_vit_kernel, cudaFuncAttributeMaxDynamicSharedMemorySize, MV_SMEM);

    embproj_kernel<<<dim3(74, 2, 1), 256, EMB_SMEM>>>(emb, Wih_f, b_f, Wih_b, b_b);
    lstm_kernel<<<148, 256, LSTM_SMEM>>>(X, lengths, Whh_f, Whh_b, h0, c0);
    mlp_vit_kernel<<<512, 256, MV_SMEM>>>(lengths, W1, b1, W2, b2, trans, out);
}